// round 11
// baseline (speedup 1.0000x reference)
#include <cuda_runtime.h>
#include <math.h>
#include <stdint.h>

#define T_STEPS 20
#define BATCH   1024
#define D_IN    2312
#define HID     512
#define OUTN    10
#define BJ0     0.01f
#define BETA_C  1.8f

// Eigen TensorContractionBlocking (threaded): kc = (16384-192)/64 = 253 -> floor8 = 248
#define KC_PANEL 248

// ---------------- device state (no allocs allowed) ----------------
__device__ float g_hin[(size_t)T_STEPS * BATCH * HID];
__device__ float g_r1_mem[BATCH * HID];
__device__ float g_r1_b[BATCH * HID];
__device__ float g_r1_spk[2][BATCH * HID];
__device__ float g_o_mem[BATCH * OUTN];
__device__ float g_o_b[BATCH * OUTN];
__device__ float g_o_spk[2][BATCH * OUTN];
__device__ float g_alpha_r1[HID], g_ro_r1[HID];
__device__ float g_alpha_o[OUTN], g_ro_o[OUTN];

// ---------------- XLA:CPU GenerateVF32Exp (cephes-Horner, fma-contracted) ----------------
// fx = floor(fma(x, log2e, 0.5)); x -= fx*C1 (fused); x -= fx*C2 (fused);
// y = 1 + (x + x^2 * Horner(p0..p5)); result = max(y * 2^fx, input).
__device__ __forceinline__ float xla_expf(float input) {
    const float exp_hi = 88.3762626647950f;
    const float exp_lo = -88.3762626647949f;
    const float LOG2EF = 1.44269504088896341f;
    const float C1 = 0.693359375f;
    const float C2 = -2.12194440e-4f;
    const float p0 = 1.9875691500E-4f;
    const float p1 = 1.3981999507E-3f;
    const float p2 = 8.3334519073E-3f;
    const float p3 = 4.1665795894E-2f;
    const float p4 = 1.6666665459E-1f;
    const float p5 = 5.0000001201E-1f;

    float x = fminf(input, exp_hi);
    x = fmaxf(x, exp_lo);
    float fx = floorf(__fmaf_rn(x, LOG2EF, 0.5f));
    x = __fmaf_rn(-C1, fx, x);       // fused: x - C1*fx
    x = __fmaf_rn(-C2, fx, x);       // fused: x - C2*fx
    float z = __fmul_rn(x, x);
    float y = __fmaf_rn(x, p0, p1);
    y = __fmaf_rn(y, x, p2);
    y = __fmaf_rn(y, x, p3);
    y = __fmaf_rn(y, x, p4);
    y = __fmaf_rn(y, x, p5);
    y = __fmaf_rn(y, z, x);
    y = __fadd_rn(1.0f, y);
    int mi = (int)fx;
    float sc = __int_as_float((mi + 127) << 23);
    return fmaxf(__fmul_rn(y, sc), input);
}

// ---------------- decay precompute (once) ----------------
__global__ void init_decay(const float* __restrict__ tau_m_r1, const float* __restrict__ tau_adp_r1,
                           const float* __restrict__ tau_m_o,  const float* __restrict__ tau_adp_o) {
    int i = threadIdx.x;
    if (i < HID) {
        g_alpha_r1[i] = xla_expf(__fdiv_rn(-1.0f, tau_m_r1[i]));
        g_ro_r1[i]    = xla_expf(__fdiv_rn(-1.0f, tau_adp_r1[i]));
    }
    if (i < OUTN) {
        g_alpha_o[i]  = xla_expf(__fdiv_rn(-1.0f, tau_m_o[i]));
        g_ro_o[i]     = xla_expf(__fdiv_rn(-1.0f, tau_adp_o[i]));
    }
}

// ---------------- Kernel 1: i2h GEMM, fp32, kc=248 panel-segmented chains ----------------
// M=20480, N=512, K=2312.  BM=128, BN=64, BK=8, 256 threads, 8x4 per thread.
__global__ __launch_bounds__(256) void gemm_i2h(const float* __restrict__ A,
                                                const float* __restrict__ W,
                                                const float* __restrict__ bias) {
    const int K = D_IN;
    __shared__ float As[8][128 + 4];
    __shared__ float Bs[8][64 + 4];

    int bm = blockIdx.y * 128;
    int bn = blockIdx.x * 64;
    int tid = threadIdx.x;

    int wid = tid >> 5, lane = tid & 31;
    int warp_m = wid & 3;
    int warp_n = wid >> 2;
    int lane_m = lane & 3;
    int lane_n = lane >> 2;
    int m0 = warp_m * 32 + lane_m * 8;
    int n0 = warp_n * 32 + lane_n * 4;

    int alr = tid >> 1, alc = (tid & 1) * 4;
    int blr = (tid & 127) >> 1, blc = ((tid & 127) & 1) * 4;
    const float* Aptr = A + (size_t)(bm + alr) * K + alc;
    const float* Wptr = W + (size_t)(bn + blr) * K + blc;

    float accT[8][4] = {};
    float accP[8][4] = {};

    for (int k0 = 0; k0 < K; k0 += 8) {
        float4 av = *(const float4*)(Aptr + k0);
        As[alc + 0][alr] = av.x; As[alc + 1][alr] = av.y;
        As[alc + 2][alr] = av.z; As[alc + 3][alr] = av.w;
        if (tid < 128) {
            float4 bv = *(const float4*)(Wptr + k0);
            Bs[blc + 0][blr] = bv.x; Bs[blc + 1][blr] = bv.y;
            Bs[blc + 2][blr] = bv.z; Bs[blc + 3][blr] = bv.w;
        }
        __syncthreads();
#pragma unroll
        for (int kk = 0; kk < 8; kk++) {
            float a[8], b[4];
#pragma unroll
            for (int i = 0; i < 8; i++) a[i] = As[kk][m0 + i];
#pragma unroll
            for (int j = 0; j < 4; j++) b[j] = Bs[kk][n0 + j];
#pragma unroll
            for (int i = 0; i < 8; i++)
#pragma unroll
                for (int j = 0; j < 4; j++) accP[i][j] = __fmaf_rn(a[i], b[j], accP[i][j]);
        }
        __syncthreads();
        if (((k0 + 8) % KC_PANEL) == 0) {
#pragma unroll
            for (int i = 0; i < 8; i++)
#pragma unroll
                for (int j = 0; j < 4; j++) {
                    accT[i][j] = __fadd_rn(accT[i][j], accP[i][j]);
                    accP[i][j] = 0.0f;
                }
        }
    }
#pragma unroll
    for (int i = 0; i < 8; i++)
#pragma unroll
        for (int j = 0; j < 4; j++) accT[i][j] = __fadd_rn(accT[i][j], accP[i][j]);

#pragma unroll
    for (int i = 0; i < 8; i++) {
        size_t row = (size_t)(bm + m0 + i) * HID;
#pragma unroll
        for (int j = 0; j < 4; j++) {
            int n = bn + n0 + j;
            g_hin[row + n] = __fadd_rn(accT[i][j], bias[n]);
        }
    }
}

// ---------------- Kernel 2: recurrent GEMM (fp32, kc=248 panels) + adaptive-LIF ------
// LIF epilogue mirrors LLVM aarch64 fma contraction (AllowFPOpFusion::Fast):
//   b'  = fma(ro, b, (1-ro)*s)
//   Bth = fma(BETA, b', BJ0)
//   mem'= fma(-Bth, s, fma(mem, alpha, (1-alpha)*h))
__global__ __launch_bounds__(256) void step_r1_kernel(int t,
        const float* __restrict__ spike_prev_arg, float* __restrict__ spike_out_arg,
        const float* __restrict__ Wh2h, const float* __restrict__ bh2h,
        const float* __restrict__ r1_mem0) {
    const float* SP = spike_prev_arg ? spike_prev_arg : g_r1_spk[(t + 1) & 1];
    float*       SO = spike_out_arg  ? spike_out_arg  : g_r1_spk[t & 1];

    __shared__ float As[8][128 + 4];
    __shared__ float Bs[8][64 + 4];

    int bm = blockIdx.y * 128;
    int bn = blockIdx.x * 64;
    int tid = threadIdx.x;

    int wid = tid >> 5, lane = tid & 31;
    int warp_m = wid & 3;
    int warp_n = wid >> 2;
    int lane_m = lane & 3;
    int lane_n = lane >> 2;
    int m0 = warp_m * 32 + lane_m * 8;
    int n0 = warp_n * 32 + lane_n * 4;

    int alr = tid >> 1, alc = (tid & 1) * 4;
    int blr = (tid & 127) >> 1, blc = ((tid & 127) & 1) * 4;
    const float* Aptr = SP   + (size_t)(bm + alr) * HID + alc;
    const float* Wptr = Wh2h + (size_t)(bn + blr) * HID + blc;

    float accT[8][4] = {};
    float accP[8][4] = {};

    for (int k0 = 0; k0 < HID; k0 += 8) {
        float4 av = *(const float4*)(Aptr + k0);
        As[alc + 0][alr] = av.x; As[alc + 1][alr] = av.y;
        As[alc + 2][alr] = av.z; As[alc + 3][alr] = av.w;
        if (tid < 128) {
            float4 bv = *(const float4*)(Wptr + k0);
            Bs[blc + 0][blr] = bv.x; Bs[blc + 1][blr] = bv.y;
            Bs[blc + 2][blr] = bv.z; Bs[blc + 3][blr] = bv.w;
        }
        __syncthreads();
#pragma unroll
        for (int kk = 0; kk < 8; kk++) {
            float a[8], b[4];
#pragma unroll
            for (int i = 0; i < 8; i++) a[i] = As[kk][m0 + i];
#pragma unroll
            for (int j = 0; j < 4; j++) b[j] = Bs[kk][n0 + j];
#pragma unroll
            for (int i = 0; i < 8; i++)
#pragma unroll
                for (int j = 0; j < 4; j++) accP[i][j] = __fmaf_rn(a[i], b[j], accP[i][j]);
        }
        __syncthreads();
        if (((k0 + 8) % KC_PANEL) == 0) {
#pragma unroll
            for (int i = 0; i < 8; i++)
#pragma unroll
                for (int j = 0; j < 4; j++) {
                    accT[i][j] = __fadd_rn(accT[i][j], accP[i][j]);
                    accP[i][j] = 0.0f;
                }
        }
    }
#pragma unroll
    for (int i = 0; i < 8; i++)
#pragma unroll
        for (int j = 0; j < 4; j++) accT[i][j] = __fadd_rn(accT[i][j], accP[i][j]);

#pragma unroll
    for (int j = 0; j < 4; j++) {
        int n = bn + n0 + j;
        float alpha = g_alpha_r1[n];
        float ro    = g_ro_r1[n];
        float one_m_alpha = __fsub_rn(1.0f, alpha);
        float one_m_ro    = __fsub_rn(1.0f, ro);
        float bias  = bh2h[n];
#pragma unroll
        for (int i = 0; i < 8; i++) {
            int m = bm + m0 + i;
            size_t idx = (size_t)m * HID + n;
            float hin   = __fadd_rn(__fadd_rn(g_hin[((size_t)m * T_STEPS + t) * HID + n],
                                              accT[i][j]), bias);
            float sp    = SP[idx];
            float bprev = (t == 0) ? BJ0 : g_r1_b[idx];
            float mprev = (t == 0) ? r1_mem0[idx] : g_r1_mem[idx];
            // contracted forms (aarch64 fmadd/fmsub):
            float bnew  = __fmaf_rn(ro, bprev, __fmul_rn(one_m_ro, sp));
            float Bth   = __fmaf_rn(BETA_C, bnew, BJ0);
            float t1    = __fmaf_rn(mprev, alpha, __fmul_rn(one_m_alpha, hin));
            float mnew  = __fmaf_rn(-Bth, sp, t1);
            float spn   = (__fsub_rn(mnew, Bth) > 0.0f) ? 1.0f : 0.0f;
            g_r1_b[idx]   = bnew;
            g_r1_mem[idx] = mnew;
            SO[idx]       = spn;
        }
    }
}

// ---------------- Kernel 3: output layer — fp32 kc=248 segmented dot, LIF, softmax ----------
__global__ __launch_bounds__(128) void step_out_kernel(int t,
        const float* __restrict__ r1_spk_cur,
        const float* __restrict__ o_spk_prev, float* __restrict__ o_spk_out,
        const float* __restrict__ Wd2o, const float* __restrict__ bd2o,
        const float* __restrict__ d2o_mem0, float* __restrict__ out_sum) {
    int warp = threadIdx.x >> 5, lane = threadIdx.x & 31;
    int b = blockIdx.x * 4 + warp;

    const float* SP    = r1_spk_cur ? r1_spk_cur : g_r1_spk[t & 1];
    const float* OPrev = o_spk_prev ? o_spk_prev : g_o_spk[(t + 1) & 1];
    float*       OOut  = o_spk_out  ? o_spk_out  : g_o_spk[t & 1];

    const float* srow = SP + (size_t)b * HID;
    float mnew = 0.0f;

    if (lane < OUTN) {
        int o = lane;
        const float* wrow = Wd2o + (size_t)o * HID;
        float acc = 0.0f, accp = 0.0f;
        for (int k = 0; k < HID; k++) {
            accp = __fmaf_rn(srow[k], wrow[k], accp);
            if (k == KC_PANEL - 1) {
                acc = __fadd_rn(acc, accp);
                accp = 0.0f;
            }
        }
        acc = __fadd_rn(acc, accp);

        float oin   = __fadd_rn(acc, bd2o[o]);
        float alpha = g_alpha_o[o];
        float ro    = g_ro_o[o];
        size_t idx  = (size_t)b * OUTN + o;
        float sp    = (t == 0) ? 0.0f : OPrev[idx];
        float bprev = (t == 0) ? BJ0 : g_o_b[idx];
        float mprev = (t == 0) ? d2o_mem0[idx] : g_o_mem[idx];
        // contracted forms:
        float bnew  = __fmaf_rn(ro, bprev, __fmul_rn(__fsub_rn(1.0f, ro), sp));
        float Bth   = __fmaf_rn(BETA_C, bnew, BJ0);
        float t1    = __fmaf_rn(mprev, alpha, __fmul_rn(__fsub_rn(1.0f, alpha), oin));
        mnew        = __fmaf_rn(-Bth, sp, t1);
        float spn   = (__fsub_rn(mnew, Bth) > 0.0f) ? 1.0f : 0.0f;
        g_o_b[idx]   = bnew;
        g_o_mem[idx] = mnew;
        OOut[idx]    = spn;
    }

    // serial softmax, ascending order, XLA exp polynomial
    float mvals[OUTN];
#pragma unroll
    for (int o = 0; o < OUTN; o++)
        mvals[o] = __shfl_sync(0xffffffffu, mnew, o);

    if (lane < OUTN) {
        size_t oi = (size_t)b * OUTN + lane;
        if (t == 0) {
            out_sum[oi] = 0.0f;
        } else {
            float mx = mvals[0];
#pragma unroll
            for (int o = 1; o < OUTN; o++) mx = fmaxf(mx, mvals[o]);
            float e[OUTN];
#pragma unroll
            for (int o = 0; o < OUTN; o++) e[o] = xla_expf(__fsub_rn(mvals[o], mx));
            float se = 0.0f;
#pragma unroll
            for (int o = 0; o < OUTN; o++) se = __fadd_rn(se, e[o]);
            out_sum[oi] = __fadd_rn(out_sum[oi], __fdiv_rn(e[lane], se));
        }
    }
}

// ---------------- launch ----------------
extern "C" void kernel_launch(void* const* d_in, const int* in_sizes, int n_in,
                              void* d_out, int out_size) {
    const float* x          = (const float*)d_in[0];
    const float* W_i2h      = (const float*)d_in[1];
    const float* b_i2h      = (const float*)d_in[2];
    const float* W_h2h      = (const float*)d_in[3];
    const float* b_h2h      = (const float*)d_in[4];
    const float* W_d2o      = (const float*)d_in[5];
    const float* b_d2o      = (const float*)d_in[6];
    const float* tau_adp_r1 = (const float*)d_in[7];
    const float* tau_m_r1   = (const float*)d_in[8];
    const float* tau_adp_o  = (const float*)d_in[9];
    const float* tau_m_o    = (const float*)d_in[10];
    const float* r1_mem0    = (const float*)d_in[11];
    const float* r1_spike0  = (const float*)d_in[12];
    const float* d2o_mem0   = (const float*)d_in[13];
    float* out = (float*)d_out;

    const long long SUMN = (long long)BATCH * OUTN;
    const long long R1N  = (long long)T_STEPS * BATCH * HID;
    const long long ON   = (long long)T_STEPS * BATCH * OUTN;
    const bool full = ((long long)out_size >= SUMN + R1N + ON);
    float* out_r1 = full ? out + SUMN : (float*)nullptr;
    float* out_o  = full ? out + SUMN + R1N : (float*)nullptr;

    init_decay<<<1, HID>>>(tau_m_r1, tau_adp_r1, tau_m_o, tau_adp_o);

    gemm_i2h<<<dim3(HID / 64, (T_STEPS * BATCH) / 128), 256>>>(x, W_i2h, b_i2h);

    for (int t = 0; t < T_STEPS; t++) {
        const float* spPrev = (t == 0) ? r1_spike0
                              : (full ? out_r1 + (size_t)(t - 1) * BATCH * HID : (float*)nullptr);
        float* spOut = full ? out_r1 + (size_t)t * BATCH * HID : (float*)nullptr;
        step_r1_kernel<<<dim3(HID / 64, BATCH / 128), 256>>>(t, spPrev, spOut,
                W_h2h, b_h2h, r1_mem0);

        const float* oPrev = (t == 0) ? (float*)nullptr
                              : (full ? out_o + (size_t)(t - 1) * BATCH * OUTN : (float*)nullptr);
        float* oOut = full ? out_o + (size_t)t * BATCH * OUTN : (float*)nullptr;
        step_out_kernel<<<BATCH / 4, 128>>>(t, spOut, oPrev, oOut,
                W_d2o, b_d2o, d2o_mem0, out);
    }
}

// round 12
// speedup vs baseline: 1.2573x; 1.2573x over previous
#include <cuda_runtime.h>
#include <math.h>
#include <stdint.h>

#define T_STEPS 20
#define BATCH   1024
#define D_IN    2312
#define HID     512
#define OUTN    10
#define BJ0     0.01f
#define BETA_C  1.8f

// Eigen TensorContractionBlocking (threaded): kc = (16384-192)/64 = 253 -> floor8 = 248.
// With BK=8 tiles, panel boundaries hit at tile index (i+1) % 31 == 0.
#define KC_PANEL 248

// ---------------- device state (no allocs allowed) ----------------
__device__ float g_hin[(size_t)T_STEPS * BATCH * HID];
__device__ float g_r1_mem[BATCH * HID];
__device__ float g_r1_b[BATCH * HID];
__device__ float g_r1_spk[2][BATCH * HID];
__device__ float g_o_mem[BATCH * OUTN];
__device__ float g_o_b[BATCH * OUTN];
__device__ float g_o_spk[2][BATCH * OUTN];
__device__ float g_alpha_r1[HID], g_ro_r1[HID];
__device__ float g_alpha_o[OUTN], g_ro_o[OUTN];

// ---------------- packed f32x2 helpers (sm_103a FFMA2 path; per-half rn semantics) -------
#define PACKF2(d, lo, hi) asm("mov.b64 %0, {%1, %2};" : "=l"(d) : "f"(lo), "f"(hi))
#define UNPACKF2(lo, hi, s) asm("mov.b64 {%0, %1}, %2;" : "=f"(lo), "=f"(hi) : "l"(s))
#define FMAF2(acc, a, b) asm("fma.rn.f32x2 %0, %1, %2, %0;" : "+l"(acc) : "l"(a), "l"(b))
#define ADDF2(d, a, b) asm("add.rn.f32x2 %0, %1, %2;" : "=l"(d) : "l"(a), "l"(b))

// ---------------- XLA:CPU GenerateVF32Exp (cephes-Horner, fma-contracted) ----------------
__device__ __forceinline__ float xla_expf(float input) {
    const float exp_hi = 88.3762626647950f;
    const float exp_lo = -88.3762626647949f;
    const float LOG2EF = 1.44269504088896341f;
    const float C1 = 0.693359375f;
    const float C2 = -2.12194440e-4f;
    const float p0 = 1.9875691500E-4f;
    const float p1 = 1.3981999507E-3f;
    const float p2 = 8.3334519073E-3f;
    const float p3 = 4.1665795894E-2f;
    const float p4 = 1.6666665459E-1f;
    const float p5 = 5.0000001201E-1f;

    float x = fminf(input, exp_hi);
    x = fmaxf(x, exp_lo);
    float fx = floorf(__fmaf_rn(x, LOG2EF, 0.5f));
    x = __fmaf_rn(-C1, fx, x);
    x = __fmaf_rn(-C2, fx, x);
    float z = __fmul_rn(x, x);
    float y = __fmaf_rn(x, p0, p1);
    y = __fmaf_rn(y, x, p2);
    y = __fmaf_rn(y, x, p3);
    y = __fmaf_rn(y, x, p4);
    y = __fmaf_rn(y, x, p5);
    y = __fmaf_rn(y, z, x);
    y = __fadd_rn(1.0f, y);
    int mi = (int)fx;
    float sc = __int_as_float((mi + 127) << 23);
    return fmaxf(__fmul_rn(y, sc), input);
}

// ---------------- decay precompute (once per launch) ----------------
__global__ void init_decay(const float* __restrict__ tau_m_r1, const float* __restrict__ tau_adp_r1,
                           const float* __restrict__ tau_m_o,  const float* __restrict__ tau_adp_o) {
    int i = threadIdx.x;
    if (i < HID) {
        g_alpha_r1[i] = xla_expf(__fdiv_rn(-1.0f, tau_m_r1[i]));
        g_ro_r1[i]    = xla_expf(__fdiv_rn(-1.0f, tau_adp_r1[i]));
    }
    if (i < OUTN) {
        g_alpha_o[i]  = xla_expf(__fdiv_rn(-1.0f, tau_m_o[i]));
        g_ro_o[i]     = xla_expf(__fdiv_rn(-1.0f, tau_adp_o[i]));
    }
}

// ---------------- Kernel 1: i2h GEMM, f32x2-packed, double-buffered, kc=248 panels ------
// M=20480, N=512, K=2312. BM=128, BN=64, BK=8, 256 threads, 8(M,paired)x4(N) per thread.
__global__ __launch_bounds__(256) void gemm_i2h(const float* __restrict__ A,
                                                const float* __restrict__ W,
                                                const float* __restrict__ bias) {
    const int K = D_IN;
    __shared__ __align__(16) float As[2][8][132];
    __shared__ __align__(16) float Bs[2][8][68];

    int bm = blockIdx.y * 128;
    int bn = blockIdx.x * 64;
    int tid = threadIdx.x;
    int wid = tid >> 5, lane = tid & 31;
    int m0 = (wid & 3) * 32 + (lane & 3) * 8;
    int n0 = (wid >> 2) * 32 + (lane >> 2) * 4;

    int alr = tid >> 1, alc = (tid & 1) * 4;
    int blr = (tid & 127) >> 1, blc = ((tid & 127) & 1) * 4;
    const float* Aptr = A + (size_t)(bm + alr) * K + alc;
    const float* Wptr = W + (size_t)(bn + blr) * K + blc;

    uint64_t accT[4][4], accP[4][4];
#pragma unroll
    for (int p = 0; p < 4; p++)
#pragma unroll
        for (int j = 0; j < 4; j++) { accT[p][j] = 0ull; accP[p][j] = 0ull; }

    const int NT = K / 8;   // 289 tiles, all full

    float4 av = *(const float4*)(Aptr);
    float4 bv = make_float4(0.f, 0.f, 0.f, 0.f);
    if (tid < 128) bv = *(const float4*)(Wptr);
    As[0][alc + 0][alr] = av.x; As[0][alc + 1][alr] = av.y;
    As[0][alc + 2][alr] = av.z; As[0][alc + 3][alr] = av.w;
    if (tid < 128) {
        Bs[0][blc + 0][blr] = bv.x; Bs[0][blc + 1][blr] = bv.y;
        Bs[0][blc + 2][blr] = bv.z; Bs[0][blc + 3][blr] = bv.w;
    }
    __syncthreads();

    for (int it = 0; it < NT; ++it) {
        int buf = it & 1;
        if (it + 1 < NT) {
            av = *(const float4*)(Aptr + (it + 1) * 8);
            if (tid < 128) bv = *(const float4*)(Wptr + (it + 1) * 8);
        }
#pragma unroll
        for (int kk = 0; kk < 8; kk++) {
            ulonglong2 aa0 = *(const ulonglong2*)&As[buf][kk][m0];
            ulonglong2 aa1 = *(const ulonglong2*)&As[buf][kk][m0 + 4];
            float4 b4 = *(const float4*)&Bs[buf][kk][n0];
            uint64_t bp0, bp1, bp2, bp3;
            PACKF2(bp0, b4.x, b4.x); PACKF2(bp1, b4.y, b4.y);
            PACKF2(bp2, b4.z, b4.z); PACKF2(bp3, b4.w, b4.w);
            uint64_t ap0 = aa0.x, ap1 = aa0.y, ap2 = aa1.x, ap3 = aa1.y;
            FMAF2(accP[0][0], ap0, bp0); FMAF2(accP[0][1], ap0, bp1);
            FMAF2(accP[0][2], ap0, bp2); FMAF2(accP[0][3], ap0, bp3);
            FMAF2(accP[1][0], ap1, bp0); FMAF2(accP[1][1], ap1, bp1);
            FMAF2(accP[1][2], ap1, bp2); FMAF2(accP[1][3], ap1, bp3);
            FMAF2(accP[2][0], ap2, bp0); FMAF2(accP[2][1], ap2, bp1);
            FMAF2(accP[2][2], ap2, bp2); FMAF2(accP[2][3], ap2, bp3);
            FMAF2(accP[3][0], ap3, bp0); FMAF2(accP[3][1], ap3, bp1);
            FMAF2(accP[3][2], ap3, bp2); FMAF2(accP[3][3], ap3, bp3);
        }
        if (((it + 1) % 31) == 0) {   // k multiple of 248: fold panel
#pragma unroll
            for (int p = 0; p < 4; p++)
#pragma unroll
                for (int j = 0; j < 4; j++) {
                    ADDF2(accT[p][j], accT[p][j], accP[p][j]);
                    accP[p][j] = 0ull;
                }
        }
        if (it + 1 < NT) {
            int nb = buf ^ 1;
            As[nb][alc + 0][alr] = av.x; As[nb][alc + 1][alr] = av.y;
            As[nb][alc + 2][alr] = av.z; As[nb][alc + 3][alr] = av.w;
            if (tid < 128) {
                Bs[nb][blc + 0][blr] = bv.x; Bs[nb][blc + 1][blr] = bv.y;
                Bs[nb][blc + 2][blr] = bv.z; Bs[nb][blc + 3][blr] = bv.w;
            }
            __syncthreads();
        }
    }
#pragma unroll
    for (int p = 0; p < 4; p++)
#pragma unroll
        for (int j = 0; j < 4; j++) ADDF2(accT[p][j], accT[p][j], accP[p][j]);

#pragma unroll
    for (int p = 0; p < 4; p++) {
        int r0 = bm + m0 + 2 * p;
#pragma unroll
        for (int j = 0; j < 4; j++) {
            int n = bn + n0 + j;
            float lo, hi;
            UNPACKF2(lo, hi, accT[p][j]);
            g_hin[(size_t)r0 * HID + n]       = __fadd_rn(lo, bias[n]);
            g_hin[(size_t)(r0 + 1) * HID + n] = __fadd_rn(hi, bias[n]);
        }
    }
}

// ---------------- Kernel 2: recurrent GEMM (f32x2, 64x64 tiles) + adaptive-LIF ----------
// M=1024, N=512, K=512. BM=BN=64, BK=8, 256 threads, 4(M,paired)x4(N)/thread. grid (8,16).
__global__ __launch_bounds__(256) void step_r1_kernel(int t,
        const float* __restrict__ spike_prev_arg, float* __restrict__ spike_out_arg,
        const float* __restrict__ Wh2h, const float* __restrict__ bh2h,
        const float* __restrict__ r1_mem0) {
    const float* SP = spike_prev_arg ? spike_prev_arg : g_r1_spk[(t + 1) & 1];
    float*       SO = spike_out_arg  ? spike_out_arg  : g_r1_spk[t & 1];

    __shared__ __align__(16) float As[2][8][68];
    __shared__ __align__(16) float Bs[2][8][68];

    int bm = blockIdx.y * 64;
    int bn = blockIdx.x * 64;
    int tid = threadIdx.x;
    int wid = tid >> 5, lane = tid & 31;
    int m0 = (wid & 3) * 16 + (lane & 3) * 4;
    int n0 = (wid >> 2) * 32 + (lane >> 2) * 4;

    int u = tid & 127;
    int lr = u >> 1, lc = (u & 1) * 4;
    bool loadB = (tid >= 128);
    const float* src = loadB ? (Wh2h + (size_t)(bn + lr) * HID + lc)
                             : (SP   + (size_t)(bm + lr) * HID + lc);

    uint64_t accT[2][4], accP[2][4];
#pragma unroll
    for (int p = 0; p < 2; p++)
#pragma unroll
        for (int j = 0; j < 4; j++) { accT[p][j] = 0ull; accP[p][j] = 0ull; }

    const int NT = HID / 8;   // 64

    float4 v = *(const float4*)(src);
    if (loadB) {
        Bs[0][lc + 0][lr] = v.x; Bs[0][lc + 1][lr] = v.y;
        Bs[0][lc + 2][lr] = v.z; Bs[0][lc + 3][lr] = v.w;
    } else {
        As[0][lc + 0][lr] = v.x; As[0][lc + 1][lr] = v.y;
        As[0][lc + 2][lr] = v.z; As[0][lc + 3][lr] = v.w;
    }
    __syncthreads();

    for (int it = 0; it < NT; ++it) {
        int buf = it & 1;
        if (it + 1 < NT) v = *(const float4*)(src + (it + 1) * 8);
#pragma unroll
        for (int kk = 0; kk < 8; kk++) {
            ulonglong2 aa = *(const ulonglong2*)&As[buf][kk][m0];
            float4 b4 = *(const float4*)&Bs[buf][kk][n0];
            uint64_t bp0, bp1, bp2, bp3;
            PACKF2(bp0, b4.x, b4.x); PACKF2(bp1, b4.y, b4.y);
            PACKF2(bp2, b4.z, b4.z); PACKF2(bp3, b4.w, b4.w);
            uint64_t ap0 = aa.x, ap1 = aa.y;
            FMAF2(accP[0][0], ap0, bp0); FMAF2(accP[0][1], ap0, bp1);
            FMAF2(accP[0][2], ap0, bp2); FMAF2(accP[0][3], ap0, bp3);
            FMAF2(accP[1][0], ap1, bp0); FMAF2(accP[1][1], ap1, bp1);
            FMAF2(accP[1][2], ap1, bp2); FMAF2(accP[1][3], ap1, bp3);
        }
        if (((it + 1) % 31) == 0) {   // k = 248, 496
#pragma unroll
            for (int p = 0; p < 2; p++)
#pragma unroll
                for (int j = 0; j < 4; j++) {
                    ADDF2(accT[p][j], accT[p][j], accP[p][j]);
                    accP[p][j] = 0ull;
                }
        }
        if (it + 1 < NT) {
            int nb = buf ^ 1;
            if (loadB) {
                Bs[nb][lc + 0][lr] = v.x; Bs[nb][lc + 1][lr] = v.y;
                Bs[nb][lc + 2][lr] = v.z; Bs[nb][lc + 3][lr] = v.w;
            } else {
                As[nb][lc + 0][lr] = v.x; As[nb][lc + 1][lr] = v.y;
                As[nb][lc + 2][lr] = v.z; As[nb][lc + 3][lr] = v.w;
            }
            __syncthreads();
        }
    }
#pragma unroll
    for (int p = 0; p < 2; p++)
#pragma unroll
        for (int j = 0; j < 4; j++) ADDF2(accT[p][j], accT[p][j], accP[p][j]);

    // LIF epilogue — contracted forms (frozen passing semantics)
#pragma unroll
    for (int j = 0; j < 4; j++) {
        int n = bn + n0 + j;
        float alpha = g_alpha_r1[n];
        float ro    = g_ro_r1[n];
        float one_m_alpha = __fsub_rn(1.0f, alpha);
        float one_m_ro    = __fsub_rn(1.0f, ro);
        float bias  = bh2h[n];
#pragma unroll
        for (int p = 0; p < 2; p++) {
            float lo, hi;
            UNPACKF2(lo, hi, accT[p][j]);
#pragma unroll
            for (int h = 0; h < 2; h++) {
                float accv = h ? hi : lo;
                int m = bm + m0 + 2 * p + h;
                size_t idx = (size_t)m * HID + n;
                float hin   = __fadd_rn(__fadd_rn(g_hin[((size_t)m * T_STEPS + t) * HID + n],
                                                  accv), bias);
                float sp    = SP[idx];
                float bprev = (t == 0) ? BJ0 : g_r1_b[idx];
                float mprev = (t == 0) ? r1_mem0[idx] : g_r1_mem[idx];
                float bnew  = __fmaf_rn(ro, bprev, __fmul_rn(one_m_ro, sp));
                float Bth   = __fmaf_rn(BETA_C, bnew, BJ0);
                float t1    = __fmaf_rn(mprev, alpha, __fmul_rn(one_m_alpha, hin));
                float mnew  = __fmaf_rn(-Bth, sp, t1);
                float spn   = (__fsub_rn(mnew, Bth) > 0.0f) ? 1.0f : 0.0f;
                g_r1_b[idx]   = bnew;
                g_r1_mem[idx] = mnew;
                SO[idx]       = spn;
            }
        }
    }
}

// ---------------- Kernel 3: output layer — thread per (b,o), weights in smem ------------
// 320 threads = 32 batch rows x 10 outputs; grid 32. Serial k chain, fold at k=247.
#define OB 32
__global__ __launch_bounds__(320) void step_out_kernel(int t,
        const float* __restrict__ r1_spk_cur,
        const float* __restrict__ o_spk_prev, float* __restrict__ o_spk_out,
        const float* __restrict__ Wd2o, const float* __restrict__ bd2o,
        const float* __restrict__ d2o_mem0, float* __restrict__ out_sum) {
    __shared__ float ws[OUTN * HID];
    __shared__ float msm[OB][OUTN];
    __shared__ float wbias[OUTN], walpha[OUTN], wro[OUTN];

    const float* SP    = r1_spk_cur ? r1_spk_cur : g_r1_spk[t & 1];
    const float* OPrev = o_spk_prev ? o_spk_prev : g_o_spk[(t + 1) & 1];
    float*       OOut  = o_spk_out  ? o_spk_out  : g_o_spk[t & 1];

    int tid = threadIdx.x;
    for (int i = tid; i < OUTN * HID; i += 320) ws[i] = Wd2o[i];
    if (tid < OUTN) {
        wbias[tid]  = bd2o[tid];
        walpha[tid] = g_alpha_o[tid];
        wro[tid]    = g_ro_o[tid];
    }
    __syncthreads();

    int bl = tid / OUTN;          // 0..31
    int o  = tid - bl * OUTN;     // 0..9
    int b  = blockIdx.x * OB + bl;

    const float4* s4 = (const float4*)(SP + (size_t)b * HID);
    const float*  wrow = ws + o * HID;

    float acc = 0.0f, accp = 0.0f;
#pragma unroll 4
    for (int q = 0; q < 62; q++) {        // k = 0..247
        float4 s = s4[q];
        int k = q * 4;
        accp = __fmaf_rn(s.x, wrow[k + 0], accp);
        accp = __fmaf_rn(s.y, wrow[k + 1], accp);
        accp = __fmaf_rn(s.z, wrow[k + 2], accp);
        accp = __fmaf_rn(s.w, wrow[k + 3], accp);
    }
    acc = __fadd_rn(acc, accp); accp = 0.0f;   // fold at k=247 (matches passing config)
#pragma unroll 4
    for (int q = 62; q < 128; q++) {      // k = 248..511
        float4 s = s4[q];
        int k = q * 4;
        accp = __fmaf_rn(s.x, wrow[k + 0], accp);
        accp = __fmaf_rn(s.y, wrow[k + 1], accp);
        accp = __fmaf_rn(s.z, wrow[k + 2], accp);
        accp = __fmaf_rn(s.w, wrow[k + 3], accp);
    }
    acc = __fadd_rn(acc, accp);

    // LIF (contracted, frozen)
    float oin   = __fadd_rn(acc, wbias[o]);
    float alpha = walpha[o];
    float ro    = wro[o];
    size_t idx  = (size_t)b * OUTN + o;
    float sp    = (t == 0) ? 0.0f : OPrev[idx];
    float bprev = (t == 0) ? BJ0 : g_o_b[idx];
    float mprev = (t == 0) ? d2o_mem0[idx] : g_o_mem[idx];
    float bnew  = __fmaf_rn(ro, bprev, __fmul_rn(__fsub_rn(1.0f, ro), sp));
    float Bth   = __fmaf_rn(BETA_C, bnew, BJ0);
    float t1    = __fmaf_rn(mprev, alpha, __fmul_rn(__fsub_rn(1.0f, alpha), oin));
    float mnew  = __fmaf_rn(-Bth, sp, t1);
    float spn   = (__fsub_rn(mnew, Bth) > 0.0f) ? 1.0f : 0.0f;
    g_o_b[idx]   = bnew;
    g_o_mem[idx] = mnew;
    OOut[idx]    = spn;
    msm[bl][o]   = mnew;
    __syncthreads();

    // serial softmax, ascending order, XLA exp polynomial (frozen op order)
    if (t == 0) {
        out_sum[idx] = 0.0f;
    } else {
        float mvals[OUTN];
#pragma unroll
        for (int q = 0; q < OUTN; q++) mvals[q] = msm[bl][q];
        float mx = mvals[0];
#pragma unroll
        for (int q = 1; q < OUTN; q++) mx = fmaxf(mx, mvals[q]);
        float e[OUTN];
#pragma unroll
        for (int q = 0; q < OUTN; q++) e[q] = xla_expf(__fsub_rn(mvals[q], mx));
        float se = 0.0f;
#pragma unroll
        for (int q = 0; q < OUTN; q++) se = __fadd_rn(se, e[q]);
        out_sum[idx] = __fadd_rn(out_sum[idx], __fdiv_rn(e[o], se));
    }
}

// ---------------- launch ----------------
extern "C" void kernel_launch(void* const* d_in, const int* in_sizes, int n_in,
                              void* d_out, int out_size) {
    const float* x          = (const float*)d_in[0];
    const float* W_i2h      = (const float*)d_in[1];
    const float* b_i2h      = (const float*)d_in[2];
    const float* W_h2h      = (const float*)d_in[3];
    const float* b_h2h      = (const float*)d_in[4];
    const float* W_d2o      = (const float*)d_in[5];
    const float* b_d2o      = (const float*)d_in[6];
    const float* tau_adp_r1 = (const float*)d_in[7];
    const float* tau_m_r1   = (const float*)d_in[8];
    const float* tau_adp_o  = (const float*)d_in[9];
    const float* tau_m_o    = (const float*)d_in[10];
    const float* r1_mem0    = (const float*)d_in[11];
    const float* r1_spike0  = (const float*)d_in[12];
    const float* d2o_mem0   = (const float*)d_in[13];
    float* out = (float*)d_out;

    const long long SUMN = (long long)BATCH * OUTN;
    const long long R1N  = (long long)T_STEPS * BATCH * HID;
    const long long ON   = (long long)T_STEPS * BATCH * OUTN;
    const bool full = ((long long)out_size >= SUMN + R1N + ON);
    float* out_r1 = full ? out + SUMN : (float*)nullptr;
    float* out_o  = full ? out + SUMN + R1N : (float*)nullptr;

    init_decay<<<1, HID>>>(tau_m_r1, tau_adp_r1, tau_m_o, tau_adp_o);

    gemm_i2h<<<dim3(HID / 64, (T_STEPS * BATCH) / 128), 256>>>(x, W_i2h, b_i2h);

    for (int t = 0; t < T_STEPS; t++) {
        const float* spPrev = (t == 0) ? r1_spike0
                              : (full ? out_r1 + (size_t)(t - 1) * BATCH * HID : (float*)nullptr);
        float* spOut = full ? out_r1 + (size_t)t * BATCH * HID : (float*)nullptr;
        step_r1_kernel<<<dim3(HID / 64, BATCH / 64), 256>>>(t, spPrev, spOut,
                W_h2h, b_h2h, r1_mem0);

        const float* oPrev = (t == 0) ? (float*)nullptr
                              : (full ? out_o + (size_t)(t - 1) * BATCH * OUTN : (float*)nullptr);
        float* oOut = full ? out_o + (size_t)t * BATCH * OUTN : (float*)nullptr;
        step_out_kernel<<<BATCH / OB, 320>>>(t, spOut, oPrev, oOut,
                W_d2o, b_d2o, d2o_mem0, out);
    }
}